// round 2
// baseline (speedup 1.0000x reference)
#include <cuda_runtime.h>
#include <math.h>
#include <float.h>

#define H 1024
#define B 32
#define S 2048
#define M_TOTAL (B * S)

// ---------------- scratch (no allocations allowed) ----------------
__device__ float g_c[B * H];        // q_proj + Wa_b + Ua_b
__device__ float g_scores[B * S];   // pre-softmax scores

// ---------------- kernel A: c[b,g] = query[b,:]·Wa_w[g,:] + Wa_b[g] + Ua_b[g]
__global__ void qproj_kernel(const float* __restrict__ query,
                             const float* __restrict__ Wa_w,
                             const float* __restrict__ Wa_b,
                             const float* __restrict__ Ua_b) {
    int warp_global = (blockIdx.x * blockDim.x + threadIdx.x) >> 5;
    int lane = threadIdx.x & 31;
    if (warp_global >= B * H) return;
    int b = warp_global >> 10;     // / H
    int g = warp_global & (H - 1);
    const float* q = query + b * H;
    const float* w = Wa_w + (size_t)g * H;
    float acc = 0.f;
    for (int h = lane * 4; h < H; h += 128) {
        float4 qv = *reinterpret_cast<const float4*>(q + h);
        float4 wv = *reinterpret_cast<const float4*>(w + h);
        acc += qv.x * wv.x + qv.y * wv.y + qv.z * wv.z + qv.w * wv.w;
    }
    #pragma unroll
    for (int o = 16; o; o >>= 1) acc += __shfl_xor_sync(0xffffffffu, acc, o);
    if (lane == 0) g_c[warp_global] = acc + Wa_b[g] + Ua_b[g];
}

// ---------------- kernel B: fused GEMM + tanh + Va reduction -> scores
// C[m,g] = keys[m,:]·Ua_w[g,:]  (both K-major, NT GEMM)
// scores[m] = sum_g tanh(C[m,g] + c[b,g]) * Va_w[g] + Va_b
#define BM 128
#define BN 128
#define BK 16
#define SPAD 132

__global__ __launch_bounds__(256, 2)
void score_gemm_kernel(const float* __restrict__ keys,
                       const float* __restrict__ Ua_w,
                       const float* __restrict__ Va_w,
                       const float* __restrict__ Va_b) {
    __shared__ float As[BK][SPAD];
    __shared__ float Bs[BK][SPAD];

    int tid = threadIdx.x;
    int tx = tid & 15;
    int ty = tid >> 4;
    int rowBase = blockIdx.x * BM;           // rows are b*S+s; BM=128 divides S
    int b = rowBase / S;
    const float* cvec = g_c + (size_t)b * H;

    float srow[8];
    #pragma unroll
    for (int i = 0; i < 8; i++) srow[i] = 0.f;

    for (int n0 = 0; n0 < H; n0 += BN) {
        float acc[8][8];
        #pragma unroll
        for (int i = 0; i < 8; i++)
            #pragma unroll
            for (int j = 0; j < 8; j++) acc[i][j] = 0.f;

        for (int k0 = 0; k0 < H; k0 += BK) {
            // load 128x16 tiles of keys (A) and Ua_w (B), transposed into smem
            #pragma unroll
            for (int it = 0; it < 2; it++) {
                int li = tid + it * 256;
                int r  = li >> 2;            // 0..127
                int kv = (li & 3) << 2;      // 0,4,8,12
                float4 v = *reinterpret_cast<const float4*>(
                    keys + (size_t)(rowBase + r) * H + k0 + kv);
                As[kv + 0][r] = v.x; As[kv + 1][r] = v.y;
                As[kv + 2][r] = v.z; As[kv + 3][r] = v.w;
                float4 u = *reinterpret_cast<const float4*>(
                    Ua_w + (size_t)(n0 + r) * H + k0 + kv);
                Bs[kv + 0][r] = u.x; Bs[kv + 1][r] = u.y;
                Bs[kv + 2][r] = u.z; Bs[kv + 3][r] = u.w;
            }
            __syncthreads();
            #pragma unroll
            for (int k = 0; k < BK; k++) {
                float4 a0 = *reinterpret_cast<const float4*>(&As[k][ty * 4]);
                float4 a1 = *reinterpret_cast<const float4*>(&As[k][64 + ty * 4]);
                float4 b0 = *reinterpret_cast<const float4*>(&Bs[k][tx * 4]);
                float4 b1 = *reinterpret_cast<const float4*>(&Bs[k][64 + tx * 4]);
                float af[8] = {a0.x, a0.y, a0.z, a0.w, a1.x, a1.y, a1.z, a1.w};
                float bf[8] = {b0.x, b0.y, b0.z, b0.w, b1.x, b1.y, b1.z, b1.w};
                #pragma unroll
                for (int i = 0; i < 8; i++)
                    #pragma unroll
                    for (int j = 0; j < 8; j++)
                        acc[i][j] += af[i] * bf[j];
            }
            __syncthreads();
        }

        // epilogue: tanh + multiply by Va, reduce over this 128-col tile
        float vw[8], cg[8];
        #pragma unroll
        for (int j = 0; j < 8; j++) {
            int gl = (j < 4) ? (tx * 4 + j) : (64 + tx * 4 + (j - 4));
            int g  = n0 + gl;
            vw[j] = Va_w[g];
            cg[j] = cvec[g];
        }
        #pragma unroll
        for (int i = 0; i < 8; i++) {
            float p = 0.f;
            #pragma unroll
            for (int j = 0; j < 8; j++)
                p += tanhf(acc[i][j] + cg[j]) * vw[j];
            p += __shfl_xor_sync(0xffffffffu, p, 1);
            p += __shfl_xor_sync(0xffffffffu, p, 2);
            p += __shfl_xor_sync(0xffffffffu, p, 4);
            p += __shfl_xor_sync(0xffffffffu, p, 8);
            srow[i] += p;
        }
    }

    if (tx == 0) {
        float vb = Va_b[0];
        #pragma unroll
        for (int i = 0; i < 8; i++) {
            int r = (i < 4) ? (ty * 4 + i) : (64 + ty * 4 + (i - 4));
            g_scores[rowBase + r] = srow[i] + vb;
        }
    }
}

// ---------------- kernel C: masked softmax over S, writes weights to d_out
__global__ void softmax_kernel(const int* __restrict__ mask,
                               float* __restrict__ weights_out) {
    int b = blockIdx.x;
    int tid = threadIdx.x;
    __shared__ float red[256];
    const float* sc = g_scores + (size_t)b * S;
    const int* mk = mask + (size_t)b * S;

    float local[8];
    float mx = -FLT_MAX;
    #pragma unroll
    for (int i = 0; i < 8; i++) {
        int s = tid + i * 256;
        float v = (mk[s] == 0) ? -FLT_MAX : sc[s];
        local[i] = v;
        mx = fmaxf(mx, v);
    }
    red[tid] = mx; __syncthreads();
    #pragma unroll
    for (int o = 128; o; o >>= 1) {
        if (tid < o) red[tid] = fmaxf(red[tid], red[tid + o]);
        __syncthreads();
    }
    mx = red[0]; __syncthreads();

    float sum = 0.f;
    #pragma unroll
    for (int i = 0; i < 8; i++) {
        float e = expf(local[i] - mx);
        local[i] = e;
        sum += e;
    }
    red[tid] = sum; __syncthreads();
    #pragma unroll
    for (int o = 128; o; o >>= 1) {
        if (tid < o) red[tid] += red[tid + o];
        __syncthreads();
    }
    float inv = 1.f / red[0];
    #pragma unroll
    for (int i = 0; i < 8; i++)
        weights_out[(size_t)b * S + tid + i * 256] = local[i] * inv;
}

// ---------------- kernel D: context[b,h] = sum_s w[b,s]*keys[b,s,h]
__global__ void context_kernel(const float* __restrict__ keys,
                               const float* __restrict__ weights,
                               float* __restrict__ ctx) {
    int b = blockIdx.y;
    int h = blockIdx.x * 256 + threadIdx.x;
    __shared__ float w_sm[S];
    for (int s = threadIdx.x; s < S; s += 256)
        w_sm[s] = weights[(size_t)b * S + s];
    __syncthreads();
    const float* kb = keys + (size_t)b * S * H + h;
    float acc = 0.f;
    #pragma unroll 16
    for (int s = 0; s < S; s++)
        acc += w_sm[s] * kb[(size_t)s * H];
    ctx[(size_t)b * H + h] = acc;
}

// ---------------- launch ----------------
extern "C" void kernel_launch(void* const* d_in, const int* in_sizes, int n_in,
                              void* d_out, int out_size) {
    const float* query = (const float*)d_in[0];
    const float* keys  = (const float*)d_in[1];
    const int*   mask  = (const int*)  d_in[2];
    const float* Wa_w  = (const float*)d_in[3];
    const float* Wa_b  = (const float*)d_in[4];
    const float* Ua_w  = (const float*)d_in[5];
    const float* Ua_b  = (const float*)d_in[6];
    const float* Va_w  = (const float*)d_in[7];
    const float* Va_b  = (const float*)d_in[8];

    float* ctx_out = (float*)d_out;              // [B,H]
    float* w_out   = (float*)d_out + B * H;      // [B,S]

    // A: q_proj + biases
    qproj_kernel<<<(B * H) / 8, 256>>>(query, Wa_w, Wa_b, Ua_b);
    // B: fused k_proj GEMM + tanh + Va reduction -> scores
    score_gemm_kernel<<<M_TOTAL / BM, 256>>>(keys, Ua_w, Va_w, Va_b);
    // C: masked softmax -> weights
    softmax_kernel<<<B, 256>>>(mask, w_out);
    // D: context = weights @ keys
    context_kernel<<<dim3(H / 256, B), 256>>>(keys, w_out, ctx_out);
}

// round 15
// speedup vs baseline: 2.4060x; 2.4060x over previous
#include <cuda_runtime.h>
#include <cuda_bf16.h>
#include <math.h>
#include <float.h>
#include <stdint.h>

#define H 1024
#define B 32
#define S 2048
#define M_TOTAL (B * S)

// ---------------- scratch ----------------
__device__ float g_c[B * H];
__device__ float g_scores[B * S];
__device__ float g_part[8 * B * H];
// packed fragment layouts (16B unit = one lane's mma fragment data)
// keys: [hl][gmblk(4096)][s(64)][lane(32)] x 16B   (words: (r,k),(r+8,k),(r,k+8),(r+8,k+8))
__device__ uint4 g_keys_p[2][4096 * 64 * 32];
// Ua:   [gn8(128)][s(64)][lane(32)] x 16B          (words: b0_hi, b1_hi, b0_lo, b1_lo)
__device__ uint4 g_ua_p[128 * 64 * 32];

__device__ __forceinline__ uint32_t pack_hi(float x0, float x1, float* r0, float* r1) {
    __nv_bfloat16 h0 = __float2bfloat16_rn(x0);
    __nv_bfloat16 h1 = __float2bfloat16_rn(x1);
    *r0 = x0 - __bfloat162float(h0);
    *r1 = x1 - __bfloat162float(h1);
    return (uint32_t)__bfloat16_as_ushort(h0) | ((uint32_t)__bfloat16_as_ushort(h1) << 16);
}
__device__ __forceinline__ uint32_t pack_bf(float x0, float x1) {
    return (uint32_t)__bfloat16_as_ushort(__float2bfloat16_rn(x0)) |
           ((uint32_t)__bfloat16_as_ushort(__float2bfloat16_rn(x1)) << 16);
}
__device__ __forceinline__ uint32_t smem_u32(const void* p) {
    uint32_t a;
    asm("{ .reg .u64 t; cvta.to.shared.u64 t, %1; cvt.u32.u64 %0, t; }" : "=r"(a) : "l"(p));
    return a;
}
__device__ __forceinline__ void cp16(uint32_t smem, const void* g) {
    asm volatile("cp.async.cg.shared.global [%0], [%1], 16;" :: "r"(smem), "l"(g));
}
#define CP_COMMIT()  asm volatile("cp.async.commit_group;" ::: "memory")
#define CP_WAIT(n)   asm volatile("cp.async.wait_group %0;" :: "n"(n) : "memory")

__device__ __forceinline__ void lds128(uint32_t* r, uint32_t addr) {
    asm volatile("ld.shared.v4.u32 {%0,%1,%2,%3}, [%4];"
                 : "=r"(r[0]), "=r"(r[1]), "=r"(r[2]), "=r"(r[3]) : "r"(addr));
}
__device__ __forceinline__ void mma16816(float* c, const uint32_t* a, uint32_t b0, uint32_t b1) {
    asm volatile("mma.sync.aligned.m16n8k16.row.col.f32.bf16.bf16.f32 "
                 "{%0,%1,%2,%3}, {%4,%5,%6,%7}, {%8,%9}, {%0,%1,%2,%3};"
                 : "+f"(c[0]), "+f"(c[1]), "+f"(c[2]), "+f"(c[3])
                 : "r"(a[0]), "r"(a[1]), "r"(a[2]), "r"(a[3]), "r"(b0), "r"(b1));
}

// ---------------- convert keys -> packed bf16 hi/lo ----------------
__global__ void keys_convert_kernel(const float* __restrict__ keys) {
    int u = blockIdx.x * 256 + threadIdx.x;     // 0 .. 4096*64*32-1
    int lane = u & 31;
    int s = (u >> 5) & 63;
    int gmblk = u >> 11;
    int r0 = gmblk * 16 + (lane >> 2);
    int k0 = s * 16 + (lane & 3) * 2;
    const float* kb = keys;
    float2 x00 = *(const float2*)(kb + (size_t)r0 * H + k0);
    float2 x01 = *(const float2*)(kb + (size_t)r0 * H + k0 + 8);
    float2 x10 = *(const float2*)(kb + (size_t)(r0 + 8) * H + k0);
    float2 x11 = *(const float2*)(kb + (size_t)(r0 + 8) * H + k0 + 8);
    float l00a, l00b, l10a, l10b, l01a, l01b, l11a, l11b;
    uint4 hi, lo;
    hi.x = pack_hi(x00.x, x00.y, &l00a, &l00b);
    hi.y = pack_hi(x10.x, x10.y, &l10a, &l10b);
    hi.z = pack_hi(x01.x, x01.y, &l01a, &l01b);
    hi.w = pack_hi(x11.x, x11.y, &l11a, &l11b);
    lo.x = pack_bf(l00a, l00b);
    lo.y = pack_bf(l10a, l10b);
    lo.z = pack_bf(l01a, l01b);
    lo.w = pack_bf(l11a, l11b);
    g_keys_p[0][u] = hi;
    g_keys_p[1][u] = lo;
}

// ---------------- convert Ua -> packed bf16 hi/lo ----------------
__global__ void ua_convert_kernel(const float* __restrict__ Ua_w) {
    int u = blockIdx.x * 256 + threadIdx.x;     // 0 .. 128*64*32-1
    int lane = u & 31;
    int s = (u >> 5) & 63;
    int gn8 = u >> 11;
    int g = gn8 * 8 + (lane >> 2);
    int k0 = s * 16 + (lane & 3) * 2;
    float2 x0 = *(const float2*)(Ua_w + (size_t)g * H + k0);
    float2 x1 = *(const float2*)(Ua_w + (size_t)g * H + k0 + 8);
    float l0a, l0b, l1a, l1b;
    uint4 w;
    w.x = pack_hi(x0.x, x0.y, &l0a, &l0b);
    w.y = pack_hi(x1.x, x1.y, &l1a, &l1b);
    w.z = pack_bf(l0a, l0b);
    w.w = pack_bf(l1a, l1b);
    g_ua_p[u] = w;
}

// ---------------- kernel A: q_proj + biases ----------------
__global__ void qproj_kernel(const float* __restrict__ query,
                             const float* __restrict__ Wa_w,
                             const float* __restrict__ Wa_b,
                             const float* __restrict__ Ua_b) {
    int warp_global = (blockIdx.x * blockDim.x + threadIdx.x) >> 5;
    int lane = threadIdx.x & 31;
    if (warp_global >= B * H) return;
    int b = warp_global >> 10;
    int g = warp_global & (H - 1);
    const float* q = query + b * H;
    const float* w = Wa_w + (size_t)g * H;
    float acc = 0.f;
    for (int h = lane * 4; h < H; h += 128) {
        float4 qv = *reinterpret_cast<const float4*>(q + h);
        float4 wv = *reinterpret_cast<const float4*>(w + h);
        acc += qv.x * wv.x + qv.y * wv.y + qv.z * wv.z + qv.w * wv.w;
    }
    #pragma unroll
    for (int o = 16; o; o >>= 1) acc += __shfl_xor_sync(0xffffffffu, acc, o);
    if (lane == 0) g_c[warp_global] = acc + Wa_b[g] + Ua_b[g];
}

// ---------------- kernel B: mma.sync bf16x3 fused score GEMM ----------------
// dyn smem: A bufs [2][hl][mblkL8][sL2][lane32]x16B = 2x16KB at 0
//           B bufs [2][gn8L16][sL2][lane32]x16B    = 2x16KB at 32768
//           ep_c[128] @65536, ep_v[128] @66048, score_sm[128] @66560
#define SC_SMEM 67072
#define OFF_B_SM 32768
#define OFF_EPC 65536
#define OFF_EPV 66048
#define OFF_SC  66560

__global__ __launch_bounds__(256, 1)
void score_mma_kernel(const float* __restrict__ Va_w,
                      const float* __restrict__ Va_b) {
    extern __shared__ char smem[];
    uint32_t sbase = smem_u32(smem);
    float* ep_c = (float*)(smem + OFF_EPC);
    float* ep_v = (float*)(smem + OFF_EPV);
    float* sc_sm = (float*)(smem + OFF_SC);

    int tid = threadIdx.x;
    int lane = tid & 31;
    int warpId = tid >> 5;
    int wmI = warpId >> 1;          // 0..3  (M 32-row block)
    int wnI = warpId & 1;           // 0..1  (N 64-col half)
    int rowBase = blockIdx.x * 128;
    int gmblk0 = blockIdx.x * 8;
    int b = rowBase >> 11;

    float sc[4] = {0.f, 0.f, 0.f, 0.f};   // row partials: [mf*2+half]

    for (int nt = 0; nt < 8; nt++) {
        __syncthreads();   // protect ep_c/ep_v from previous epilogue readers

        // prologue: chunk 0 into buf0
        #pragma unroll
        for (int i = 0; i < 4; i++) {
            int unit = tid + i * 256;               // A: 0..1023
            int hl = unit >> 9, rem = unit & 511;
            int mbL = rem >> 6, t64 = rem & 63;
            cp16(sbase + hl * 8192 + mbL * 1024 + t64 * 16,
                 &g_keys_p[hl][(size_t)(gmblk0 + mbL) * 2048 + t64]);
            int gn8L = unit >> 6, bt = unit & 63;   // B: 0..1023
            cp16(sbase + OFF_B_SM + gn8L * 1024 + bt * 16,
                 &g_ua_p[(size_t)(nt * 16 + gn8L) * 2048 + bt]);
        }
        CP_COMMIT();

        if (tid < 128) {
            int g = nt * 128 + tid;
            ep_c[tid] = g_c[b * 1024 + g];
            ep_v[tid] = Va_w[g];
        }

        float c[2][8][4];
        #pragma unroll
        for (int mf = 0; mf < 2; mf++)
            #pragma unroll
            for (int nf = 0; nf < 8; nf++)
                #pragma unroll
                for (int j = 0; j < 4; j++) c[mf][nf][j] = 0.f;

        for (int kc = 0; kc < 32; kc++) {
            int p = kc & 1;
            if (kc + 1 < 32) {
                int pa = (kc + 1) & 1;
                #pragma unroll
                for (int i = 0; i < 4; i++) {
                    int unit = tid + i * 256;
                    int hl = unit >> 9, rem = unit & 511;
                    int mbL = rem >> 6, t64 = rem & 63;
                    cp16(sbase + pa * 16384 + hl * 8192 + mbL * 1024 + t64 * 16,
                         &g_keys_p[hl][(size_t)(gmblk0 + mbL) * 2048 + (kc + 1) * 64 + t64]);
                    int gn8L = unit >> 6, bt = unit & 63;
                    cp16(sbase + OFF_B_SM + pa * 16384 + gn8L * 1024 + bt * 16,
                         &g_ua_p[(size_t)(nt * 16 + gn8L) * 2048 + (kc + 1) * 64 + bt]);
                }
                CP_COMMIT();
                CP_WAIT(1);
            } else {
                CP_WAIT(0);
            }
            __syncthreads();

            uint32_t aBufBase = sbase + p * 16384;
            uint32_t bBufBase = sbase + OFF_B_SM + p * 16384;
            #pragma unroll
            for (int s = 0; s < 2; s++) {
                uint32_t ah[2][4], al[2][4];
                #pragma unroll
                for (int mf = 0; mf < 2; mf++) {
                    int mb = wmI * 2 + mf;
                    lds128(ah[mf], aBufBase + mb * 1024 + s * 512 + lane * 16);
                    lds128(al[mf], aBufBase + 8192 + mb * 1024 + s * 512 + lane * 16);
                }
                #pragma unroll
                for (int nf = 0; nf < 8; nf++) {
                    uint32_t bb[4];
                    int gn8L = wnI * 8 + nf;
                    lds128(bb, bBufBase + gn8L * 1024 + s * 512 + lane * 16);
                    #pragma unroll
                    for (int mf = 0; mf < 2; mf++) {
                        mma16816(c[mf][nf], ah[mf], bb[0], bb[1]);   // hi*hi
                        mma16816(c[mf][nf], ah[mf], bb[2], bb[3]);   // hi*lo
                        mma16816(c[mf][nf], al[mf], bb[0], bb[1]);   // lo*hi
                    }
                }
            }
            __syncthreads();
        }

        // epilogue: tanh + Va reduction for this 128-col tile
        #pragma unroll
        for (int mf = 0; mf < 2; mf++) {
            #pragma unroll
            for (int nf = 0; nf < 8; nf++) {
                int gl = wnI * 64 + nf * 8 + (lane & 3) * 2;
                float cg0 = ep_c[gl],     vw0 = ep_v[gl];
                float cg1 = ep_c[gl + 1], vw1 = ep_v[gl + 1];
                #pragma unroll
                for (int j = 0; j < 4; j++) {
                    float d = c[mf][nf][j] + ((j & 1) ? cg1 : cg0);
                    float xe = fminf(fmaxf(d * 2.885390082f, -40.f), 40.f);
                    float e;
                    asm("ex2.approx.f32 %0, %1;" : "=f"(e) : "f"(xe));
                    float rc;
                    asm("rcp.approx.f32 %0, %1;" : "=f"(rc) : "f"(e + 1.0f));
                    float t = (e - 1.0f) * rc * ((j & 1) ? vw1 : vw0);
                    sc[mf * 2 + (j >> 1)] += t;
                }
            }
        }
    }

    // reduce across the 4-lane column groups
    #pragma unroll
    for (int j = 0; j < 4; j++) {
        sc[j] += __shfl_xor_sync(0xffffffffu, sc[j], 1);
        sc[j] += __shfl_xor_sync(0xffffffffu, sc[j], 2);
    }
    // combine the two N-half warps via smem, then write
    if (wnI == 1 && (lane & 3) == 0) {
        #pragma unroll
        for (int j = 0; j < 4; j++) {
            int rloc = wmI * 32 + (j >> 1) * 16 + (j & 1) * 8 + (lane >> 2);
            sc_sm[rloc] = sc[j];
        }
    }
    __syncthreads();
    if (wnI == 0 && (lane & 3) == 0) {
        float vb = Va_b[0];
        #pragma unroll
        for (int j = 0; j < 4; j++) {
            int rloc = wmI * 32 + (j >> 1) * 16 + (j & 1) * 8 + (lane >> 2);
            g_scores[rowBase + rloc] = sc[j] + sc_sm[rloc] + vb;
        }
    }
}

// ---------------- kernel C: masked softmax ----------------
__global__ void softmax_kernel(const int* __restrict__ mask,
                               float* __restrict__ weights_out) {
    int b = blockIdx.x;
    int tid = threadIdx.x;
    __shared__ float red[256];
    const float* sc = g_scores + (size_t)b * S;
    const int* mk = mask + (size_t)b * S;

    float local[8];
    float mx = -FLT_MAX;
    #pragma unroll
    for (int i = 0; i < 8; i++) {
        int s = tid + i * 256;
        float v = (mk[s] == 0) ? -FLT_MAX : sc[s];
        local[i] = v;
        mx = fmaxf(mx, v);
    }
    red[tid] = mx; __syncthreads();
    #pragma unroll
    for (int o = 128; o; o >>= 1) {
        if (tid < o) red[tid] = fmaxf(red[tid], red[tid + o]);
        __syncthreads();
    }
    mx = red[0]; __syncthreads();

    float sum = 0.f;
    #pragma unroll
    for (int i = 0; i < 8; i++) {
        float e = expf(local[i] - mx);
        local[i] = e;
        sum += e;
    }
    red[tid] = sum; __syncthreads();
    #pragma unroll
    for (int o = 128; o; o >>= 1) {
        if (tid < o) red[tid] += red[tid + o];
        __syncthreads();
    }
    float inv = 1.f / red[0];
    #pragma unroll
    for (int i = 0; i < 8; i++)
        weights_out[(size_t)b * S + tid + i * 256] = local[i] * inv;
}

// ---------------- kernel D: context partials + reduce ----------------
__global__ void context_part_kernel(const float* __restrict__ keys,
                                    const float* __restrict__ weights) {
    int ss = blockIdx.x;
    int b = blockIdx.y;
    int tid = threadIdx.x;
    __shared__ float w_sm[256];
    w_sm[tid] = weights[(size_t)b * S + ss * 256 + tid];
    __syncthreads();
    const float* kb = keys + ((size_t)b * S + ss * 256) * H + tid * 4;
    float ax = 0.f, ay = 0.f, az = 0.f, aw = 0.f;
    #pragma unroll 8
    for (int s = 0; s < 256; s++) {
        float4 kv = *reinterpret_cast<const float4*>(kb + (size_t)s * H);
        float w = w_sm[s];
        ax += w * kv.x; ay += w * kv.y; az += w * kv.z; aw += w * kv.w;
    }
    *reinterpret_cast<float4*>(g_part + ((size_t)ss * B + b) * H + tid * 4) =
        make_float4(ax, ay, az, aw);
}

__global__ void context_reduce_kernel(float* __restrict__ ctx) {
    int i = blockIdx.x * 256 + threadIdx.x;
    float a = 0.f;
    #pragma unroll
    for (int p = 0; p < 8; p++) a += g_part[(size_t)p * B * H + i];
    ctx[i] = a;
}

// ---------------- launch ----------------
extern "C" void kernel_launch(void* const* d_in, const int* in_sizes, int n_in,
                              void* d_out, int out_size) {
    const float* query = (const float*)d_in[0];
    const float* keys  = (const float*)d_in[1];
    const int*   mask  = (const int*)  d_in[2];
    const float* Wa_w  = (const float*)d_in[3];
    const float* Wa_b  = (const float*)d_in[4];
    const float* Ua_w  = (const float*)d_in[5];
    const float* Ua_b  = (const float*)d_in[6];
    const float* Va_w  = (const float*)d_in[7];
    const float* Va_b  = (const float*)d_in[8];

    float* ctx_out = (float*)d_out;              // [B,H]
    float* w_out   = (float*)d_out + B * H;      // [B,S]

    cudaFuncSetAttribute(score_mma_kernel,
                         cudaFuncAttributeMaxDynamicSharedMemorySize, SC_SMEM);

    ua_convert_kernel<<<1024, 256>>>(Ua_w);
    keys_convert_kernel<<<32768, 256>>>(keys);
    qproj_kernel<<<(B * H) / 8, 256>>>(query, Wa_w, Wa_b, Ua_b);
    score_mma_kernel<<<M_TOTAL / 128, 256, SC_SMEM>>>(Va_w, Va_b);
    softmax_kernel<<<B, 256>>>(mask, w_out);
    context_part_kernel<<<dim3(8, B), 256>>>(keys, w_out);
    context_reduce_kernel<<<(B * H) / 256, 256>>>(ctx_out);
}